// round 4
// baseline (speedup 1.0000x reference)
#include <cuda_runtime.h>
#include <stdint.h>

// ---------------- problem constants ----------------
#define N_BINS    84
#define NBP       96        // bins padded to 16*6
#define FFTLEN    2048
#define FREQ_BINS 1025
#define HOP       512
#define T_SAMPLES 8388608
#define N_FRAMES  16381

// ---------------- fused kernel W storage ----------------
// Layout: Wg[n][bin][2] = {Wr, Wi},  n in [0,2048), bin in [0,96)
__device__ float Wg[FFTLEN * NBP * 2];

// ---------------- f32x2 helpers ----------------
__device__ __forceinline__ uint64_t dup2(float x) {
    uint64_t r; asm("mov.b64 %0, {%1, %1};" : "=l"(r) : "f"(x)); return r;
}
__device__ __forceinline__ void unpack2(uint64_t v, float& lo, float& hi) {
    asm("mov.b64 {%0, %1}, %2;" : "=f"(lo), "=f"(hi) : "l"(v));
}
__device__ __forceinline__ void ffma2(uint64_t& acc, uint64_t a, uint64_t b) {
    asm("fma.rn.f32x2 %0, %1, %2, %0;" : "+l"(acc) : "l"(a), "l"(b));
}

// =====================================================================
// Kernel 1: precompute fused kernels
//   Wr[b,n] = sum_k kr[b,k]*wcos[k,n] - ki[b,k]*wsin[k,n]
//   Wi[b,n] = sum_k kr[b,k]*wsin[k,n] + ki[b,k]*wcos[k,n]
// 256 CTAs x 256 threads; CTA = 8 n-cols x 96 bins; thread = 1 col x 3 bins.
// Smem holds PRE-DUPLICATED operands so inner loop is LDS.128 + FFMA2 only:
//   kct[bin][kl] = {kr,kr,ki,ki}   wct[kl][n] = {c, s, -s, c}
//   acc(re,im):  re += kr*c - ki*s ; im += kr*s + ki*c
// =====================================================================
#define P_NT   8
#define P_KT   32
#define P_KCT  (NBP * P_KT * 4)         // 12288 floats
#define P_WCT  (P_KT * P_NT * 4)        // 1024 floats
#define P_SMEM ((P_KCT + P_WCT) * 4)    // 53248 bytes

__global__ void __launch_bounds__(256) prep_kernel(
    const float* __restrict__ kr, const float* __restrict__ ki,
    const float* __restrict__ wcos, const float* __restrict__ wsin)
{
    extern __shared__ float psm[];
    float* kct = psm;                 // [96][32][4]
    float* wct = psm + P_KCT;         // [32][8][4]

    const int tid   = threadIdx.x;
    const int n_t   = tid & 7;
    const int bin_t = tid >> 3;       // 0..31, 3 bins each
    const int n0    = blockIdx.x * P_NT;

    uint64_t acc[3] = {0ull, 0ull, 0ull};

    for (int kt = 0; kt < 33; kt++) {         // 33*32 = 1056 >= 1025
        const int k0 = kt * P_KT;
        __syncthreads();
        // fill kct: coalesced gmem (kl contiguous), conflict-free STS.128
        for (int i = tid; i < NBP * P_KT; i += 256) {
            int b = i >> 5, kl = i & 31, kg = k0 + kl;
            float vr = 0.f, vi = 0.f;
            if (b < N_BINS && kg < FREQ_BINS) {
                vr = kr[b * FREQ_BINS + kg];
                vi = ki[b * FREQ_BINS + kg];
            }
            reinterpret_cast<float4*>(kct)[b * P_KT + kl] =
                make_float4(vr, vr, vi, vi);
        }
        // fill wct
        {
            int i = tid;                       // 256 entries exactly
            int kl = i >> 3, nn = i & 7, kg = k0 + kl;
            float c = 0.f, s = 0.f;
            if (kg < FREQ_BINS) {
                c = wcos[kg * FFTLEN + n0 + nn];
                s = wsin[kg * FFTLEN + n0 + nn];
            }
            reinterpret_cast<float4*>(wct)[kl * P_NT + nn] =
                make_float4(c, s, -s, c);
        }
        __syncthreads();
#pragma unroll 4
        for (int kl = 0; kl < P_KT; kl++) {
            ulonglong2 w =
                reinterpret_cast<const ulonglong2*>(wct)[kl * P_NT + n_t];
            const ulonglong2* kp =
                reinterpret_cast<const ulonglong2*>(kct) + (bin_t * 3) * P_KT + kl;
            ulonglong2 kv0 = kp[0];
            ulonglong2 kv1 = kp[P_KT];
            ulonglong2 kv2 = kp[2 * P_KT];
            ffma2(acc[0], kv0.x, w.x); ffma2(acc[0], kv0.y, w.y);
            ffma2(acc[1], kv1.x, w.x); ffma2(acc[1], kv1.y, w.y);
            ffma2(acc[2], kv2.x, w.x); ffma2(acc[2], kv2.y, w.y);
        }
    }
    const int n = n0 + n_t;
#pragma unroll
    for (int i = 0; i < 3; i++) {
        int b = bin_t * 3 + i;
        float wr, wi; unpack2(acc[i], wr, wi);
        Wg[n * (NBP * 2) + b * 2]     = wr;   // b>=84 stays exactly 0
        Wg[n * (NBP * 2) + b * 2 + 1] = wi;
    }
}

// =====================================================================
// Kernel 2: main CQT
//   out[b,f] = sqrt(Re^2 + Im^2),  (Re,Im)[b,f] = sum_n x[f*512+n]*W[b,n]
// CTA tile: 32 frames x 96 bins. 256 threads = 16 frame_t x 16 bin_t.
// Thread computes 2 frames x 6 bins, (re,im) packed as f32x2.
// KT=16 W tiles double-buffered via registers -> 96.4KB smem -> 2 CTAs/SM.
// =====================================================================
#define FT       32
#define KT       16
#define NTILES   (FFTLEN / KT)    // 128
#define XROWS    35               // FT + 3
#define XSTRIDE  513              // odd stride -> conflict-free strided reads
#define WS_OFF   17956            // XROWS*XSTRIDE=17955, +1 pad -> 16B aligned
#define WBUF     (KT * NBP * 2)   // 3072 floats per buffer
#define M_SMEM   ((WS_OFF + 2 * WBUF) * 4)   // 96400 bytes

__global__ void __launch_bounds__(256, 2) cqt_main(
    const float* __restrict__ x, float* __restrict__ out)
{
    extern __shared__ float sm[];
    float* xs = sm;             // [XROWS][XSTRIDE]
    float* ws = sm + WS_OFF;    // [2][KT][NBP][2]

    const int tid     = threadIdx.x;
    const int frame_t = tid & 15;
    const int bin_t   = tid >> 4;
    const int f0      = blockIdx.x * FT;
    const int base    = f0 * HOP;

    // ---- load x window: rows g = f0 .. f0+34, 512 floats each ----
    for (int i = tid; i < XROWS * 512; i += 256) {
        int row = i >> 9, m = i & 511;
        int g = base + row * 512 + m;
        xs[row * XSTRIDE + m] = (g < T_SAMPLES) ? x[g] : 0.f;
    }

    // ---- prefetch W tile 0 ----
    const float4* wgv = reinterpret_cast<const float4*>(Wg);
    float4 pf[3];
#pragma unroll
    for (int q = 0; q < 3; q++) pf[q] = wgv[tid + 256 * q];
    {
        float4* wsv = reinterpret_cast<float4*>(ws);
#pragma unroll
        for (int q = 0; q < 3; q++) wsv[tid + 256 * q] = pf[q];
    }
    __syncthreads();

    uint64_t acc[2][6];
#pragma unroll
    for (int r = 0; r < 2; r++)
#pragma unroll
        for (int i = 0; i < 6; i++) acc[r][i] = 0ull;

    for (int t = 0; t < NTILES; t++) {
        const int cur = t & 1;
        // prefetch next tile into registers
        if (t < NTILES - 1) {
            const float4* p = wgv + (t + 1) * (KT * 48);
#pragma unroll
            for (int q = 0; q < 3; q++) pf[q] = p[tid + 256 * q];
        }
        const int n0 = t * KT;
        const int j  = n0 >> 9;          // constant within tile (512 % KT == 0)
        const int m0 = n0 & 511;
        const float* xb0 = &xs[(frame_t + j) * XSTRIDE + m0];
        const float* xb1 = xb0 + 16 * XSTRIDE;
        const float* wb  = &ws[cur * WBUF + bin_t * 12];
#pragma unroll 8
        for (int kk = 0; kk < KT; kk++) {
            uint64_t x0 = dup2(xb0[kk]);
            uint64_t x1 = dup2(xb1[kk]);
            const ulonglong2* wp =
                reinterpret_cast<const ulonglong2*>(wb + kk * (NBP * 2));
            ulonglong2 w01 = wp[0];
            ulonglong2 w23 = wp[1];
            ulonglong2 w45 = wp[2];
            ffma2(acc[0][0], w01.x, x0); ffma2(acc[1][0], w01.x, x1);
            ffma2(acc[0][1], w01.y, x0); ffma2(acc[1][1], w01.y, x1);
            ffma2(acc[0][2], w23.x, x0); ffma2(acc[1][2], w23.x, x1);
            ffma2(acc[0][3], w23.y, x0); ffma2(acc[1][3], w23.y, x1);
            ffma2(acc[0][4], w45.x, x0); ffma2(acc[1][4], w45.x, x1);
            ffma2(acc[0][5], w45.y, x0); ffma2(acc[1][5], w45.y, x1);
        }
        // write prefetched tile to the other buffer
        if (t < NTILES - 1) {
            float4* wsv = reinterpret_cast<float4*>(ws + (cur ^ 1) * WBUF);
#pragma unroll
            for (int q = 0; q < 3; q++) wsv[tid + 256 * q] = pf[q];
        }
        __syncthreads();
    }

    // ---- magnitude + store ----
#pragma unroll
    for (int r = 0; r < 2; r++) {
        int f = f0 + frame_t + 16 * r;
        if (f >= N_FRAMES) continue;
#pragma unroll
        for (int i = 0; i < 6; i++) {
            int b = bin_t * 6 + i;
            if (b < N_BINS) {
                float re, im; unpack2(acc[r][i], re, im);
                out[b * N_FRAMES + f] = sqrtf(re * re + im * im);
            }
        }
    }
}

// =====================================================================
extern "C" void kernel_launch(void* const* d_in, const int* in_sizes, int n_in,
                              void* d_out, int out_size)
{
    const float* x    = (const float*)d_in[0];
    const float* wcos = (const float*)d_in[1];
    const float* wsin = (const float*)d_in[2];
    const float* kr   = (const float*)d_in[3];
    const float* ki   = (const float*)d_in[4];
    float* out = (float*)d_out;

    cudaFuncSetAttribute(prep_kernel,
                         cudaFuncAttributeMaxDynamicSharedMemorySize, P_SMEM);
    prep_kernel<<<FFTLEN / P_NT, 256, P_SMEM>>>(kr, ki, wcos, wsin);

    cudaFuncSetAttribute(cqt_main,
                         cudaFuncAttributeMaxDynamicSharedMemorySize, M_SMEM);
    cqt_main<<<(16384 / FT), 256, M_SMEM>>>(x, out);
}

// round 5
// speedup vs baseline: 1.0004x; 1.0004x over previous
#include <cuda_runtime.h>
#include <stdint.h>

// ---------------- problem constants ----------------
#define N_BINS    84
#define NBP       96        // bins padded to 16*6
#define FFTLEN    2048
#define FREQ_BINS 1025
#define HOP       512
#define T_SAMPLES 8388608
#define N_FRAMES  16381

// ---------------- fused kernel W storage ----------------
// Layout: Wg[n][bin][2] = {Wr, Wi},  n in [0,2048), bin in [0,96)
__device__ float Wg[FFTLEN * NBP * 2];

// ---------------- f32x2 helpers ----------------
__device__ __forceinline__ uint64_t dup2(float x) {
    uint64_t r; asm("mov.b64 %0, {%1, %1};" : "=l"(r) : "f"(x)); return r;
}
__device__ __forceinline__ void unpack2(uint64_t v, float& lo, float& hi) {
    asm("mov.b64 {%0, %1}, %2;" : "=f"(lo), "=f"(hi) : "l"(v));
}
__device__ __forceinline__ void ffma2(uint64_t& acc, uint64_t a, uint64_t b) {
    asm("fma.rn.f32x2 %0, %1, %2, %0;" : "+l"(acc) : "l"(a), "l"(b));
}

// =====================================================================
// Kernel 1: precompute fused kernels
//   Wr[b,n] = sum_k kr[b,k]*wcos[k,n] - ki[b,k]*wsin[k,n]
//   Wi[b,n] = sum_k kr[b,k]*wsin[k,n] + ki[b,k]*wcos[k,n]
// 256 CTAs x 256 threads; CTA = 8 n-cols x 96 bins; thread = 1 col x 3 bins.
// Smem holds PRE-DUPLICATED operands so inner loop is LDS.128 + FFMA2 only:
//   kct[bin][kl] = {kr,kr,ki,ki}   wct[kl][n] = {c, s, -s, c}
//   acc(re,im):  re += kr*c - ki*s ; im += kr*s + ki*c
// =====================================================================
#define P_NT   8
#define P_KT   32
#define P_KCT  (NBP * P_KT * 4)         // 12288 floats
#define P_WCT  (P_KT * P_NT * 4)        // 1024 floats
#define P_SMEM ((P_KCT + P_WCT) * 4)    // 53248 bytes

__global__ void __launch_bounds__(256) prep_kernel(
    const float* __restrict__ kr, const float* __restrict__ ki,
    const float* __restrict__ wcos, const float* __restrict__ wsin)
{
    extern __shared__ float psm[];
    float* kct = psm;                 // [96][32][4]
    float* wct = psm + P_KCT;         // [32][8][4]

    const int tid   = threadIdx.x;
    const int n_t   = tid & 7;
    const int bin_t = tid >> 3;       // 0..31, 3 bins each
    const int n0    = blockIdx.x * P_NT;

    uint64_t acc[3] = {0ull, 0ull, 0ull};

    for (int kt = 0; kt < 33; kt++) {         // 33*32 = 1056 >= 1025
        const int k0 = kt * P_KT;
        __syncthreads();
        // fill kct: coalesced gmem (kl contiguous), conflict-free STS.128
        for (int i = tid; i < NBP * P_KT; i += 256) {
            int b = i >> 5, kl = i & 31, kg = k0 + kl;
            float vr = 0.f, vi = 0.f;
            if (b < N_BINS && kg < FREQ_BINS) {
                vr = kr[b * FREQ_BINS + kg];
                vi = ki[b * FREQ_BINS + kg];
            }
            reinterpret_cast<float4*>(kct)[b * P_KT + kl] =
                make_float4(vr, vr, vi, vi);
        }
        // fill wct
        {
            int i = tid;                       // 256 entries exactly
            int kl = i >> 3, nn = i & 7, kg = k0 + kl;
            float c = 0.f, s = 0.f;
            if (kg < FREQ_BINS) {
                c = wcos[kg * FFTLEN + n0 + nn];
                s = wsin[kg * FFTLEN + n0 + nn];
            }
            reinterpret_cast<float4*>(wct)[kl * P_NT + nn] =
                make_float4(c, s, -s, c);
        }
        __syncthreads();
#pragma unroll 4
        for (int kl = 0; kl < P_KT; kl++) {
            ulonglong2 w =
                reinterpret_cast<const ulonglong2*>(wct)[kl * P_NT + n_t];
            const ulonglong2* kp =
                reinterpret_cast<const ulonglong2*>(kct) + (bin_t * 3) * P_KT + kl;
            ulonglong2 kv0 = kp[0];
            ulonglong2 kv1 = kp[P_KT];
            ulonglong2 kv2 = kp[2 * P_KT];
            ffma2(acc[0], kv0.x, w.x); ffma2(acc[0], kv0.y, w.y);
            ffma2(acc[1], kv1.x, w.x); ffma2(acc[1], kv1.y, w.y);
            ffma2(acc[2], kv2.x, w.x); ffma2(acc[2], kv2.y, w.y);
        }
    }
    const int n = n0 + n_t;
#pragma unroll
    for (int i = 0; i < 3; i++) {
        int b = bin_t * 3 + i;
        float wr, wi; unpack2(acc[i], wr, wi);
        Wg[n * (NBP * 2) + b * 2]     = wr;   // b>=84 stays exactly 0
        Wg[n * (NBP * 2) + b * 2 + 1] = wi;
    }
}

// =====================================================================
// Kernel 2: main CQT
//   out[b,f] = sqrt(Re^2 + Im^2),  (Re,Im)[b,f] = sum_n x[f*512+n]*W[b,n]
// CTA tile: 32 frames x 96 bins. 256 threads = 16 frame_t x 16 bin_t.
// Thread computes 2 frames x 6 bins, (re,im) packed as f32x2.
// KT=16 W tiles double-buffered via registers -> 96.4KB smem -> 2 CTAs/SM.
// =====================================================================
#define FT       32
#define KT       16
#define NTILES   (FFTLEN / KT)    // 128
#define XROWS    35               // FT + 3
#define XSTRIDE  513              // odd stride -> conflict-free strided reads
#define WS_OFF   17956            // XROWS*XSTRIDE=17955, +1 pad -> 16B aligned
#define WBUF     (KT * NBP * 2)   // 3072 floats per buffer
#define M_SMEM   ((WS_OFF + 2 * WBUF) * 4)   // 96400 bytes

__global__ void __launch_bounds__(256, 2) cqt_main(
    const float* __restrict__ x, float* __restrict__ out)
{
    extern __shared__ float sm[];
    float* xs = sm;             // [XROWS][XSTRIDE]
    float* ws = sm + WS_OFF;    // [2][KT][NBP][2]

    const int tid     = threadIdx.x;
    const int frame_t = tid & 15;
    const int bin_t   = tid >> 4;
    const int f0      = blockIdx.x * FT;
    const int base    = f0 * HOP;

    // ---- load x window: rows g = f0 .. f0+34, 512 floats each ----
    for (int i = tid; i < XROWS * 512; i += 256) {
        int row = i >> 9, m = i & 511;
        int g = base + row * 512 + m;
        xs[row * XSTRIDE + m] = (g < T_SAMPLES) ? x[g] : 0.f;
    }

    // ---- prefetch W tile 0 ----
    const float4* wgv = reinterpret_cast<const float4*>(Wg);
    float4 pf[3];
#pragma unroll
    for (int q = 0; q < 3; q++) pf[q] = wgv[tid + 256 * q];
    {
        float4* wsv = reinterpret_cast<float4*>(ws);
#pragma unroll
        for (int q = 0; q < 3; q++) wsv[tid + 256 * q] = pf[q];
    }
    __syncthreads();

    uint64_t acc[2][6];
#pragma unroll
    for (int r = 0; r < 2; r++)
#pragma unroll
        for (int i = 0; i < 6; i++) acc[r][i] = 0ull;

    for (int t = 0; t < NTILES; t++) {
        const int cur = t & 1;
        // prefetch next tile into registers
        if (t < NTILES - 1) {
            const float4* p = wgv + (t + 1) * (KT * 48);
#pragma unroll
            for (int q = 0; q < 3; q++) pf[q] = p[tid + 256 * q];
        }
        const int n0 = t * KT;
        const int j  = n0 >> 9;          // constant within tile (512 % KT == 0)
        const int m0 = n0 & 511;
        const float* xb0 = &xs[(frame_t + j) * XSTRIDE + m0];
        const float* xb1 = xb0 + 16 * XSTRIDE;
        const float* wb  = &ws[cur * WBUF + bin_t * 12];
#pragma unroll 8
        for (int kk = 0; kk < KT; kk++) {
            uint64_t x0 = dup2(xb0[kk]);
            uint64_t x1 = dup2(xb1[kk]);
            const ulonglong2* wp =
                reinterpret_cast<const ulonglong2*>(wb + kk * (NBP * 2));
            ulonglong2 w01 = wp[0];
            ulonglong2 w23 = wp[1];
            ulonglong2 w45 = wp[2];
            ffma2(acc[0][0], w01.x, x0); ffma2(acc[1][0], w01.x, x1);
            ffma2(acc[0][1], w01.y, x0); ffma2(acc[1][1], w01.y, x1);
            ffma2(acc[0][2], w23.x, x0); ffma2(acc[1][2], w23.x, x1);
            ffma2(acc[0][3], w23.y, x0); ffma2(acc[1][3], w23.y, x1);
            ffma2(acc[0][4], w45.x, x0); ffma2(acc[1][4], w45.x, x1);
            ffma2(acc[0][5], w45.y, x0); ffma2(acc[1][5], w45.y, x1);
        }
        // write prefetched tile to the other buffer
        if (t < NTILES - 1) {
            float4* wsv = reinterpret_cast<float4*>(ws + (cur ^ 1) * WBUF);
#pragma unroll
            for (int q = 0; q < 3; q++) wsv[tid + 256 * q] = pf[q];
        }
        __syncthreads();
    }

    // ---- magnitude + store ----
#pragma unroll
    for (int r = 0; r < 2; r++) {
        int f = f0 + frame_t + 16 * r;
        if (f >= N_FRAMES) continue;
#pragma unroll
        for (int i = 0; i < 6; i++) {
            int b = bin_t * 6 + i;
            if (b < N_BINS) {
                float re, im; unpack2(acc[r][i], re, im);
                out[b * N_FRAMES + f] = sqrtf(re * re + im * im);
            }
        }
    }
}

// =====================================================================
extern "C" void kernel_launch(void* const* d_in, const int* in_sizes, int n_in,
                              void* d_out, int out_size)
{
    const float* x    = (const float*)d_in[0];
    const float* wcos = (const float*)d_in[1];
    const float* wsin = (const float*)d_in[2];
    const float* kr   = (const float*)d_in[3];
    const float* ki   = (const float*)d_in[4];
    float* out = (float*)d_out;

    cudaFuncSetAttribute(prep_kernel,
                         cudaFuncAttributeMaxDynamicSharedMemorySize, P_SMEM);
    prep_kernel<<<FFTLEN / P_NT, 256, P_SMEM>>>(kr, ki, wcos, wsin);

    cudaFuncSetAttribute(cqt_main,
                         cudaFuncAttributeMaxDynamicSharedMemorySize, M_SMEM);
    cqt_main<<<(16384 / FT), 256, M_SMEM>>>(x, out);
}

// round 7
// speedup vs baseline: 1.6429x; 1.6422x over previous
#include <cuda_runtime.h>
#include <cuda_bf16.h>
#include <stdint.h>

// ---------------- problem constants ----------------
#define N_BINS    84
#define NBP       96
#define FFTLEN    2048
#define FREQ_BINS 1025
#define HOP       512
#define T_SAMPLES 8388608
#define N_FRAMES  16381
#define CHUNKS    64          // 64 chunks x 32 base-k = 2048

// ---------------- device globals ----------------
// x split into bf16 hi/lo
__device__ __nv_bfloat16 xh_b[T_SAMPLES];          // 16 MB
__device__ __nv_bfloat16 xl_b[T_SAMPLES];          // 16 MB
// B (fused W) in mma-fragment order, bf16:
// [chunk][k16(2)][half(2)][ntile(24)][lane(32)][reg(2)*2 bf16]  -> 24576 B/chunk
__device__ __align__(128) __nv_bfloat16 Bbig[CHUNKS * 2 * 2 * 24 * 32 * 4];  // 1.5 MB

// ---------------- f32x2 helpers (prep) ----------------
__device__ __forceinline__ uint64_t pack2(float lo, float hi) {
    uint64_t r; asm("mov.b64 %0, {%1, %2};" : "=l"(r) : "f"(lo), "f"(hi)); return r;
}
__device__ __forceinline__ uint64_t dup2(float x) {
    uint64_t r; asm("mov.b64 %0, {%1, %1};" : "=l"(r) : "f"(x)); return r;
}
__device__ __forceinline__ void unpack2(uint64_t v, float& lo, float& hi) {
    asm("mov.b64 {%0, %1}, %2;" : "=f"(lo), "=f"(hi) : "l"(v));
}
__device__ __forceinline__ void ffma2(uint64_t& acc, uint64_t a, uint64_t b) {
    asm("fma.rn.f32x2 %0, %1, %2, %0;" : "+l"(acc) : "l"(a), "l"(b));
}
__device__ __forceinline__ uint32_t smem_u32(const void* p) {
    uint32_t a;
    asm("{ .reg .u64 t; cvta.to.shared.u64 t, %1; cvt.u32.u64 %0, t; }"
        : "=r"(a) : "l"(p));
    return a;
}

// =====================================================================
// Kernel 0: split x into bf16 hi/lo
// =====================================================================
__global__ void __launch_bounds__(256) prep_x(const float* __restrict__ x) {
    int i = (blockIdx.x * 256 + threadIdx.x) * 8;
    float4 a = *reinterpret_cast<const float4*>(x + i);
    float4 c = *reinterpret_cast<const float4*>(x + i + 4);
    float v[8] = {a.x, a.y, a.z, a.w, c.x, c.y, c.z, c.w};
#pragma unroll
    for (int j = 0; j < 4; j++) {
        __nv_bfloat16 h0 = __float2bfloat16(v[2 * j]);
        __nv_bfloat16 h1 = __float2bfloat16(v[2 * j + 1]);
        __nv_bfloat16 l0 = __float2bfloat16(v[2 * j]     - __bfloat162float(h0));
        __nv_bfloat16 l1 = __float2bfloat16(v[2 * j + 1] - __bfloat162float(h1));
        *reinterpret_cast<__nv_bfloat162*>(xh_b + i + 2 * j) = __nv_bfloat162(h0, h1);
        *reinterpret_cast<__nv_bfloat162*>(xl_b + i + 2 * j) = __nv_bfloat162(l0, l1);
    }
}

// =====================================================================
// Kernel 1: fused kernel precompute (verified R2 core).
//   Wr[b,kg] = sum_q kr[b,q]*wcos[q,kg] - ki[b,q]*wsin[q,kg]
//   Wi[b,kg] = sum_q kr[b,q]*wsin[q,kg] + ki[b,q]*wcos[q,kg]
// Tail writes Bbig in m16n8k16 B-fragment order, bf16 hi/lo split.
//   column 2b = Wr, 2b+1 = Wi.
// =====================================================================
__device__ __forceinline__ void storeB(int kg, int col,
                                       __nv_bfloat16 h, __nv_bfloat16 l) {
    int chunk = kg >> 5, k16 = (kg >> 4) & 1, kc = (kg & 15) >> 1;
    int reg = kc >> 2, byte = kg & 1;
    int lane = ((col & 7) << 2) | (kc & 3);
    int nt = col >> 3;
    int base = ((((chunk * 2 + k16) * 2) * 24 + nt) * 32 + lane) * 4 + reg * 2 + byte;
    Bbig[base] = h;                       // half 0 (hi)
    Bbig[base + 24 * 32 * 4] = l;         // half 1 (lo)
}

__global__ void __launch_bounds__(256) prep_kernel(
    const float* __restrict__ kr, const float* __restrict__ ki,
    const float* __restrict__ wcos, const float* __restrict__ wsin)
{
    __shared__ float kct[32 * NBP * 2];
    __shared__ float wct[32 * 16 * 2];

    const int tid   = threadIdx.x;
    const int n_t   = tid & 15;
    const int bin_t = tid >> 4;
    const int n0    = blockIdx.x * 16;

    uint64_t acc[6];
#pragma unroll
    for (int i = 0; i < 6; i++) acc[i] = 0ull;

    for (int kt = 0; kt < 33; kt++) {
        const int k0 = kt * 32;
        __syncthreads();
        for (int i = tid; i < NBP * 32; i += 256) {
            int b = i >> 5, kl = i & 31, kg = k0 + kl;
            float vr = 0.f, vi = 0.f;
            if (b < N_BINS && kg < FREQ_BINS) {
                vr = kr[b * FREQ_BINS + kg];
                vi = ki[b * FREQ_BINS + kg];
            }
            kct[kl * (NBP * 2) + b * 2]     = vr;
            kct[kl * (NBP * 2) + b * 2 + 1] = vi;
        }
        for (int i = tid; i < 32 * 16; i += 256) {
            int kl = i >> 4, nn = i & 15, kg = k0 + kl;
            float c = 0.f, s = 0.f;
            if (kg < FREQ_BINS) {
                c = wcos[kg * FFTLEN + n0 + nn];
                s = wsin[kg * FFTLEN + n0 + nn];
            }
            wct[kl * 32 + nn * 2]     = c;
            wct[kl * 32 + nn * 2 + 1] = s;
        }
        __syncthreads();
#pragma unroll 4
        for (int kl = 0; kl < 32; kl++) {
            float c = wct[kl * 32 + n_t * 2];
            float s = wct[kl * 32 + n_t * 2 + 1];
            uint64_t cs  = pack2(c, s);
            uint64_t mcs = pack2(-s, c);
            const float* kp = &kct[kl * (NBP * 2) + bin_t * 12];
#pragma unroll
            for (int i = 0; i < 6; i++) {
                float vkr = kp[i * 2], vki = kp[i * 2 + 1];
                ffma2(acc[i], dup2(vkr), cs);
                ffma2(acc[i], dup2(vki), mcs);
            }
        }
    }
    const int kg = n0 + n_t;
#pragma unroll
    for (int i = 0; i < 6; i++) {
        int b = bin_t * 6 + i;            // b >= 84 rows are exact zeros
        float wr, wi; unpack2(acc[i], wr, wi);
        __nv_bfloat16 hr = __float2bfloat16(wr);
        __nv_bfloat16 lr = __float2bfloat16(wr - __bfloat162float(hr));
        __nv_bfloat16 hi_ = __float2bfloat16(wi);
        __nv_bfloat16 li_ = __float2bfloat16(wi - __bfloat162float(hi_));
        storeB(kg, 2 * b,     hr, lr);
        storeB(kg, 2 * b + 1, hi_, li_);
    }
}

// =====================================================================
// Kernel 2: bf16 mma.sync GEMM.
//   CTA: 128 frames x 192 cols. 8 warps = 4m x 2n, warp tile 32x96.
//   K: 64 chunks of 32 base-k; per chunk 3 products (Ah*Bh, Ah*Bl, Al*Bh).
//   A smem layout [k16][half][mtile(8)][lane(32)][reg(4)] u32 (frag order)
//   B smem layout [k16][half][ntile(24)][lane(32)][reg(2)] u32 (frag order)
// =====================================================================
#define A_ST   4096                 // u32: 16 KB
#define B_ST   6144                 // u32: 24 KB
#define STAGE  (A_ST + B_ST)        // 10240 u32 = 40 KB
#define MM_SMEM (2 * STAGE * 4)     // 81920 bytes

__device__ __forceinline__ void mma16816(float* d, const uint32_t* a,
                                         const uint32_t* b) {
    asm volatile(
        "mma.sync.aligned.m16n8k16.row.col.f32.bf16.bf16.f32 "
        "{%0,%1,%2,%3}, {%4,%5,%6,%7}, {%8,%9}, {%0,%1,%2,%3};"
        : "+f"(d[0]), "+f"(d[1]), "+f"(d[2]), "+f"(d[3])
        : "r"(a[0]), "r"(a[1]), "r"(a[2]), "r"(a[3]), "r"(b[0]), "r"(b[1]));
}

__device__ __forceinline__ void fill_stage(int c, uint32_t* buf, uint32_t bsm,
                                           int f0, int tid) {
    // ---- A: 128 rows x 32 k, hi+lo, into fragment order ----
    const int row = tid & 127, half = tid >> 7;
    const __nv_bfloat16* src = half ? xl_b : xh_b;
    const int g = (f0 + row) * HOP + c * 32;
    const uint4* p = reinterpret_cast<const uint4*>(src + g);
    uint32_t v[16];
#pragma unroll
    for (int i = 0; i < 4; i++) {
        uint4 t = make_uint4(0u, 0u, 0u, 0u);
        if (g + i * 8 + 7 < T_SAMPLES) t = p[i];
        v[i * 4 + 0] = t.x; v[i * 4 + 1] = t.y;
        v[i * 4 + 2] = t.z; v[i * 4 + 3] = t.w;
    }
    const int mtile = row >> 4;
    const int rb    = (row >> 3) & 1;
    const int lhw   = (row & 7) << 2;
#pragma unroll
    for (int cp = 0; cp < 16; cp++) {
        int k16 = cp >> 3, kc = cp & 7;
        int ln  = lhw | (kc & 3);
        int reg = ((kc >> 2) << 1) | rb;
        buf[(((k16 * 2 + half) * 8 + mtile) * 32 + ln) * 4 + reg] = v[cp];
    }
    // ---- B: straight cp.async copy of pre-fragmented 24 KB blob ----
    const char* bs = reinterpret_cast<const char*>(Bbig) + (size_t)c * 24576;
    uint32_t bd = bsm + A_ST * 4;
#pragma unroll
    for (int i = 0; i < 6; i++) {
        int e = tid + i * 256;
        asm volatile("cp.async.ca.shared.global [%0], [%1], 16;"
                     :: "r"(bd + e * 16), "l"(bs + e * 16) : "memory");
    }
    asm volatile("cp.async.commit_group;" ::: "memory");
}

__global__ void __launch_bounds__(256) cqt_mma(float* __restrict__ out) {
    extern __shared__ uint32_t sm[];
    const int tid  = threadIdx.x;
    const int lane = tid & 31, wid = tid >> 5;
    const int wm   = wid & 3,  wn  = wid >> 2;
    const int f0   = blockIdx.x * 128;
    const uint32_t smb = smem_u32(sm);

    float acc[2][12][4];
#pragma unroll
    for (int a = 0; a < 2; a++)
#pragma unroll
        for (int b = 0; b < 12; b++)
#pragma unroll
            for (int d = 0; d < 4; d++) acc[a][b][d] = 0.f;

    fill_stage(0, sm, smb, f0, tid);

    for (int c = 0; c < CHUNKS; c++) {
        uint32_t* cur = sm + (c & 1) * STAGE;
        if (c + 1 < CHUNKS) {
            fill_stage(c + 1, sm + ((c + 1) & 1) * STAGE,
                       smb + ((c + 1) & 1) * STAGE * 4, f0, tid);
            asm volatile("cp.async.wait_group 1;" ::: "memory");
        } else {
            asm volatile("cp.async.wait_group 0;" ::: "memory");
        }
        __syncthreads();

        const uint32_t* A = cur;
        const uint32_t* B = cur + A_ST;
#pragma unroll
        for (int k16 = 0; k16 < 2; k16++) {
            uint32_t af[2][4];
            // Ah fragments (both mtiles of this warp)
#pragma unroll
            for (int mt = 0; mt < 2; mt++) {
                uint4 q = *reinterpret_cast<const uint4*>(
                    A + (((k16 * 2 + 0) * 8 + wm * 2 + mt) * 32 + lane) * 4);
                af[mt][0] = q.x; af[mt][1] = q.y; af[mt][2] = q.z; af[mt][3] = q.w;
            }
            // Ah*Bh then Ah*Bl
#pragma unroll
            for (int bh = 0; bh < 2; bh++) {
#pragma unroll
                for (int nt = 0; nt < 12; nt++) {
                    uint2 bq = *reinterpret_cast<const uint2*>(
                        B + (((k16 * 2 + bh) * 24 + wn * 12 + nt) * 32 + lane) * 2);
                    uint32_t bf[2] = {bq.x, bq.y};
                    mma16816(acc[0][nt], af[0], bf);
                    mma16816(acc[1][nt], af[1], bf);
                }
            }
            // Al fragments, Al*Bh
#pragma unroll
            for (int mt = 0; mt < 2; mt++) {
                uint4 q = *reinterpret_cast<const uint4*>(
                    A + (((k16 * 2 + 1) * 8 + wm * 2 + mt) * 32 + lane) * 4);
                af[mt][0] = q.x; af[mt][1] = q.y; af[mt][2] = q.z; af[mt][3] = q.w;
            }
#pragma unroll
            for (int nt = 0; nt < 12; nt++) {
                uint2 bq = *reinterpret_cast<const uint2*>(
                    B + (((k16 * 2 + 0) * 24 + wn * 12 + nt) * 32 + lane) * 2);
                uint32_t bf[2] = {bq.x, bq.y};
                mma16816(acc[0][nt], af[0], bf);
                mma16816(acc[1][nt], af[1], bf);
            }
        }
        __syncthreads();
    }

    // ---- epilogue: magnitude + store ----
#pragma unroll
    for (int mt = 0; mt < 2; mt++) {
        int fr = f0 + wm * 32 + mt * 16 + (lane >> 2);
#pragma unroll
        for (int nt = 0; nt < 12; nt++) {
            int bin = wn * 48 + nt * 4 + (lane & 3);
            if (bin < N_BINS) {
                float* d = acc[mt][nt];
                if (fr < N_FRAMES)
                    out[bin * N_FRAMES + fr] = sqrtf(d[0] * d[0] + d[1] * d[1]);
                if (fr + 8 < N_FRAMES)
                    out[bin * N_FRAMES + fr + 8] = sqrtf(d[2] * d[2] + d[3] * d[3]);
            }
        }
    }
}

// =====================================================================
extern "C" void kernel_launch(void* const* d_in, const int* in_sizes, int n_in,
                              void* d_out, int out_size)
{
    const float* x    = (const float*)d_in[0];
    const float* wcos = (const float*)d_in[1];
    const float* wsin = (const float*)d_in[2];
    const float* kr   = (const float*)d_in[3];
    const float* ki   = (const float*)d_in[4];
    float* out = (float*)d_out;

    prep_x<<<T_SAMPLES / 2048, 256>>>(x);
    prep_kernel<<<FFTLEN / 16, 256>>>(kr, ki, wcos, wsin);

    cudaFuncSetAttribute(cqt_mma, cudaFuncAttributeMaxDynamicSharedMemorySize,
                         MM_SMEM);
    cqt_mma<<<16384 / 128, 256, MM_SMEM>>>(out);
}

// round 8
// speedup vs baseline: 1.7266x; 1.0509x over previous
#include <cuda_runtime.h>
#include <cuda_bf16.h>
#include <stdint.h>

// ---------------- problem constants ----------------
#define N_BINS    84
#define FFTLEN    2048
#define FREQ_BINS 1025
#define HOP       512
#define T_SAMPLES 8388608
#define N_FRAMES  16381
#define CHUNKS    64          // 64 chunks x 32 base-k = 2048
#define NTL       22          // ntiles: 176 cols = 88 re/im pairs >= 84 bins
#define NBPAD     96          // prep inner padding (16*6)

// ---------------- device globals ----------------
__device__ __nv_bfloat16 xh_b[T_SAMPLES];          // 16 MB
__device__ __nv_bfloat16 xl_b[T_SAMPLES];          // 16 MB
// B fragments: [chunk][k16(2)][bh(2)][nt(22)][lane(32)][reg(2) u32]
__device__ __align__(128) __nv_bfloat16 Bbig[CHUNKS * 2 * 2 * NTL * 32 * 4];

// ---------------- f32x2 helpers (prep) ----------------
__device__ __forceinline__ uint64_t pack2(float lo, float hi) {
    uint64_t r; asm("mov.b64 %0, {%1, %2};" : "=l"(r) : "f"(lo), "f"(hi)); return r;
}
__device__ __forceinline__ uint64_t dup2(float x) {
    uint64_t r; asm("mov.b64 %0, {%1, %1};" : "=l"(r) : "f"(x)); return r;
}
__device__ __forceinline__ void unpack2(uint64_t v, float& lo, float& hi) {
    asm("mov.b64 {%0, %1}, %2;" : "=f"(lo), "=f"(hi) : "l"(v));
}
__device__ __forceinline__ void ffma2(uint64_t& acc, uint64_t a, uint64_t b) {
    asm("fma.rn.f32x2 %0, %1, %2, %0;" : "+l"(acc) : "l"(a), "l"(b));
}

// =====================================================================
// storeB: write one (col, k) fused-W value into fragment order (verified R7)
// =====================================================================
__device__ __forceinline__ void storeB(int kg, int col,
                                       __nv_bfloat16 h, __nv_bfloat16 l) {
    int chunk = kg >> 5, k16 = (kg >> 4) & 1, kc = (kg & 15) >> 1;
    int reg = kc >> 2, byte = kg & 1;
    int lane = ((col & 7) << 2) | (kc & 3);
    int nt = col >> 3;
    // bf16 index: u32_index*2 + byte ; bh=1 (lo) offset = NTL*32*2 u32
    int u32i = (((chunk * 2 + k16) * 2) * NTL + nt) * 64 + lane * 2 + reg;
    Bbig[u32i * 2 + byte] = h;
    Bbig[(u32i + NTL * 64) * 2 + byte] = l;
}

// =====================================================================
// Kernel: merged prep.  CTAs [0,128): fused-W build (verified R2 core);
// CTAs [128, 128+4096): x bf16 hi/lo split (memory-bound, hides under W).
// =====================================================================
__global__ void __launch_bounds__(256) prep_all(
    const float* __restrict__ x,
    const float* __restrict__ kr, const float* __restrict__ ki,
    const float* __restrict__ wcos, const float* __restrict__ wsin)
{
    __shared__ float kct[32 * NBPAD * 2];
    __shared__ float wct[32 * 16 * 2];
    const int tid = threadIdx.x;

    if (blockIdx.x >= 128) {
        // ---------- x split ----------
        int i = ((blockIdx.x - 128) * 256 + tid) * 8;
        float4 a = *reinterpret_cast<const float4*>(x + i);
        float4 c = *reinterpret_cast<const float4*>(x + i + 4);
        float v[8] = {a.x, a.y, a.z, a.w, c.x, c.y, c.z, c.w};
#pragma unroll
        for (int j = 0; j < 4; j++) {
            __nv_bfloat16 h0 = __float2bfloat16(v[2 * j]);
            __nv_bfloat16 h1 = __float2bfloat16(v[2 * j + 1]);
            __nv_bfloat16 l0 = __float2bfloat16(v[2 * j]     - __bfloat162float(h0));
            __nv_bfloat16 l1 = __float2bfloat16(v[2 * j + 1] - __bfloat162float(h1));
            *reinterpret_cast<__nv_bfloat162*>(xh_b + i + 2 * j) = __nv_bfloat162(h0, h1);
            *reinterpret_cast<__nv_bfloat162*>(xl_b + i + 2 * j) = __nv_bfloat162(l0, l1);
        }
        return;
    }

    // ---------- fused-W build ----------
    const int n_t   = tid & 15;
    const int bin_t = tid >> 4;
    const int n0    = blockIdx.x * 16;

    uint64_t acc[6];
#pragma unroll
    for (int i = 0; i < 6; i++) acc[i] = 0ull;

    for (int kt = 0; kt < 33; kt++) {
        const int k0 = kt * 32;
        __syncthreads();
        for (int i = tid; i < NBPAD * 32; i += 256) {
            int b = i >> 5, kl = i & 31, kg = k0 + kl;
            float vr = 0.f, vi = 0.f;
            if (b < N_BINS && kg < FREQ_BINS) {
                vr = kr[b * FREQ_BINS + kg];
                vi = ki[b * FREQ_BINS + kg];
            }
            kct[kl * (NBPAD * 2) + b * 2]     = vr;
            kct[kl * (NBPAD * 2) + b * 2 + 1] = vi;
        }
        for (int i = tid; i < 32 * 16; i += 256) {
            int kl = i >> 4, nn = i & 15, kg = k0 + kl;
            float c = 0.f, s = 0.f;
            if (kg < FREQ_BINS) {
                c = wcos[kg * FFTLEN + n0 + nn];
                s = wsin[kg * FFTLEN + n0 + nn];
            }
            wct[kl * 32 + nn * 2]     = c;
            wct[kl * 32 + nn * 2 + 1] = s;
        }
        __syncthreads();
#pragma unroll 4
        for (int kl = 0; kl < 32; kl++) {
            float c = wct[kl * 32 + n_t * 2];
            float s = wct[kl * 32 + n_t * 2 + 1];
            uint64_t cs  = pack2(c, s);
            uint64_t mcs = pack2(-s, c);
            const float* kp = &kct[kl * (NBPAD * 2) + bin_t * 12];
#pragma unroll
            for (int i = 0; i < 6; i++) {
                float vkr = kp[i * 2], vki = kp[i * 2 + 1];
                ffma2(acc[i], dup2(vkr), cs);
                ffma2(acc[i], dup2(vki), mcs);
            }
        }
    }
    const int kg = n0 + n_t;
#pragma unroll
    for (int i = 0; i < 6; i++) {
        int b = bin_t * 6 + i;
        if (b >= N_BINS) continue;         // cols >= 168 stay zero (padding)
        float wr, wi; unpack2(acc[i], wr, wi);
        __nv_bfloat16 hr = __float2bfloat16(wr);
        __nv_bfloat16 lr = __float2bfloat16(wr - __bfloat162float(hr));
        __nv_bfloat16 hw = __float2bfloat16(wi);
        __nv_bfloat16 lw = __float2bfloat16(wi - __bfloat162float(hw));
        storeB(kg, 2 * b,     hr, lr);
        storeB(kg, 2 * b + 1, hw, lw);
    }
}

// =====================================================================
// Main GEMM: CTA = 64 frames x 176 cols, 128 threads (4 warps = 2m x 2n).
// Warp tile 32 x 88: mt=2 mtiles, nt=11 ntiles, K split 3-product bf16.
//   A smem u32[k16][half][mtile(4)][128-block, XOR-swizzled]
//   B smem u32[k16][bh][nt(22)][lane][reg(2)]  (straight cp.async of Bbig)
// Pipeline: LDG A two chunks ahead (regs), STS one ahead; cp.async B one
// ahead; single __syncthreads per chunk.
// =====================================================================
#define A_ST   2048                 // u32 per A stage (8 KB)
#define B_ST   (2 * 2 * NTL * 64)   // 5632 u32 (22 KB)
#define STAGE  (A_ST + B_ST)        // 7680 u32 (30 KB)
#define MM_SMEM (2 * STAGE * 4)     // 61440 bytes

__device__ __forceinline__ void mma16816(float* d, const uint32_t* a,
                                         const uint32_t* b) {
    asm volatile(
        "mma.sync.aligned.m16n8k16.row.col.f32.bf16.bf16.f32 "
        "{%0,%1,%2,%3}, {%4,%5,%6,%7}, {%8,%9}, {%0,%1,%2,%3};"
        : "+f"(d[0]), "+f"(d[1]), "+f"(d[2]), "+f"(d[3])
        : "r"(a[0]), "r"(a[1]), "r"(a[2]), "r"(a[3]), "r"(b[0]), "r"(b[1]));
}

__device__ __forceinline__ void lda(int c, int f0, int tid, uint32_t* va) {
    const int row = tid & 63, half = tid >> 6;
    const __nv_bfloat16* src = half ? xl_b : xh_b;
    const int g = (f0 + row) * HOP + c * 32;
    const uint4* p = reinterpret_cast<const uint4*>(src + g);
#pragma unroll
    for (int i = 0; i < 4; i++) {
        uint4 t = make_uint4(0u, 0u, 0u, 0u);
        if (g + i * 8 + 7 < T_SAMPLES) t = p[i];
        va[i * 4 + 0] = t.x; va[i * 4 + 1] = t.y;
        va[i * 4 + 2] = t.z; va[i * 4 + 3] = t.w;
    }
}

__device__ __forceinline__ void sts_a(const uint32_t* va, uint32_t* bufA, int tid) {
    const int row = tid & 63, half = tid >> 6;
    const int mtile = row >> 4;
    const int rb = (row >> 3) & 1;
    const int rl = row & 7;
#pragma unroll
    for (int cp = 0; cp < 16; cp++) {
        int k16 = cp >> 3, kc = cp & 7;
        int ln  = (rl << 2) | (kc & 3);
        int reg = ((kc >> 2) << 1) | rb;
        int p   = (ln << 2) | reg;
        p ^= ((p >> 5) & 3) << 2;          // bank swizzle
        bufA[((k16 * 2 + half) * 4 + mtile) * 128 + p] = va[cp];
    }
}

__global__ void __launch_bounds__(128, 2) cqt_mma(float* __restrict__ out) {
    extern __shared__ uint32_t sm[];
    const int tid  = threadIdx.x;
    const int lane = tid & 31, wid = tid >> 5;
    const int wm   = wid & 1,  wn  = wid >> 1;
    const int f0   = blockIdx.x * 64;

    float acc[2][11][4];
#pragma unroll
    for (int a = 0; a < 2; a++)
#pragma unroll
        for (int b = 0; b < 11; b++)
#pragma unroll
            for (int d = 0; d < 4; d++) acc[a][b][d] = 0.f;

    uint32_t va[16];

    // prologue: A(0) -> stage0, B(0) in flight, A(1) in regs
    lda(0, f0, tid, va);
    sts_a(va, sm, tid);
    {
        const char* bs = reinterpret_cast<const char*>(Bbig);
        uint32_t bd;
        asm("{ .reg .u64 t; cvta.to.shared.u64 t, %1; cvt.u32.u64 %0, t; }"
            : "=r"(bd) : "l"((const void*)(sm + A_ST)));
#pragma unroll
        for (int i = 0; i < 11; i++) {
            int e = tid + i * 128;
            asm volatile("cp.async.ca.shared.global [%0], [%1], 16;"
                         :: "r"(bd + e * 16), "l"(bs + e * 16) : "memory");
        }
        asm volatile("cp.async.commit_group;" ::: "memory");
    }
    lda(1, f0, tid, va);

    for (int c = 0; c < CHUNKS; c++) {
        asm volatile("cp.async.wait_group 0;" ::: "memory");
        __syncthreads();   // A(c)+B(c) visible; compute(c-1) done by all

        if (c < CHUNKS - 1) {
            uint32_t* nbuf = sm + ((c + 1) & 1) * STAGE;
            sts_a(va, nbuf, tid);
            const char* bs = reinterpret_cast<const char*>(Bbig)
                             + (size_t)(c + 1) * (B_ST * 4);
            uint32_t bd;
            asm("{ .reg .u64 t; cvta.to.shared.u64 t, %1; cvt.u32.u64 %0, t; }"
                : "=r"(bd) : "l"((const void*)(nbuf + A_ST)));
#pragma unroll
            for (int i = 0; i < 11; i++) {
                int e = tid + i * 128;
                asm volatile("cp.async.ca.shared.global [%0], [%1], 16;"
                             :: "r"(bd + e * 16), "l"(bs + e * 16) : "memory");
            }
            asm volatile("cp.async.commit_group;" ::: "memory");
        }
        if (c < CHUNKS - 2) lda(c + 2, f0, tid, va);

        const uint32_t* A = sm + (c & 1) * STAGE;
        const uint32_t* B = A + A_ST;
#pragma unroll
        for (int k16 = 0; k16 < 2; k16++) {
            uint32_t ah[2][4], al[2][4];
            const int psw = (lane * 4) ^ ((((lane * 4) >> 5) & 3) << 2);
#pragma unroll
            for (int mt = 0; mt < 2; mt++) {
                uint4 qh = *reinterpret_cast<const uint4*>(
                    A + ((k16 * 2 + 0) * 4 + wm * 2 + mt) * 128 + psw);
                ah[mt][0] = qh.x; ah[mt][1] = qh.y; ah[mt][2] = qh.z; ah[mt][3] = qh.w;
                uint4 ql = *reinterpret_cast<const uint4*>(
                    A + ((k16 * 2 + 1) * 4 + wm * 2 + mt) * 128 + psw);
                al[mt][0] = ql.x; al[mt][1] = ql.y; al[mt][2] = ql.z; al[mt][3] = ql.w;
            }
#pragma unroll
            for (int nt = 0; nt < 11; nt++) {
                int bi = ((k16 * 2) * NTL + wn * 11 + nt) * 64 + lane * 2;
                uint2 qh = *reinterpret_cast<const uint2*>(B + bi);
                uint2 ql = *reinterpret_cast<const uint2*>(B + bi + NTL * 64);
                uint32_t bh[2] = {qh.x, qh.y};
                uint32_t bl[2] = {ql.x, ql.y};
                mma16816(acc[0][nt], ah[0], bh);
                mma16816(acc[1][nt], ah[1], bh);
                mma16816(acc[0][nt], al[0], bh);
                mma16816(acc[1][nt], al[1], bh);
                mma16816(acc[0][nt], ah[0], bl);
                mma16816(acc[1][nt], ah[1], bl);
            }
        }
    }

    // ---- epilogue: magnitude + store ----
#pragma unroll
    for (int mt = 0; mt < 2; mt++) {
        int fr = f0 + wm * 32 + mt * 16 + (lane >> 2);
#pragma unroll
        for (int nt = 0; nt < 11; nt++) {
            int bin = wn * 44 + nt * 4 + (lane & 3);
            if (bin < N_BINS) {
                float* d = acc[mt][nt];
                if (fr < N_FRAMES)
                    out[bin * N_FRAMES + fr] = sqrtf(d[0] * d[0] + d[1] * d[1]);
                if (fr + 8 < N_FRAMES)
                    out[bin * N_FRAMES + fr + 8] = sqrtf(d[2] * d[2] + d[3] * d[3]);
            }
        }
    }
}

// =====================================================================
extern "C" void kernel_launch(void* const* d_in, const int* in_sizes, int n_in,
                              void* d_out, int out_size)
{
    const float* x    = (const float*)d_in[0];
    const float* wcos = (const float*)d_in[1];
    const float* wsin = (const float*)d_in[2];
    const float* kr   = (const float*)d_in[3];
    const float* ki   = (const float*)d_in[4];
    float* out = (float*)d_out;

    prep_all<<<128 + T_SAMPLES / 2048, 256>>>(x, kr, ki, wcos, wsin);

    cudaFuncSetAttribute(cqt_mma, cudaFuncAttributeMaxDynamicSharedMemorySize,
                         MM_SMEM);
    cqt_mma<<<16384 / 64, 128, MM_SMEM>>>(out);
}

// round 9
// speedup vs baseline: 2.2745x; 1.3173x over previous
#include <cuda_runtime.h>
#include <cuda_bf16.h>
#include <stdint.h>

// ---------------- problem constants ----------------
#define N_BINS    84
#define FFTLEN    2048
#define FREQ_BINS 1025
#define HOP       512
#define T_SAMPLES 8388608
#define N_FRAMES  16381
#define CHUNKS    64          // 64 chunks x 32 base-k = 2048
#define NTL       22          // ntiles: 176 cols = 88 re/im pairs >= 84 bins
#define NBPAD     96          // prep inner padding (16*6)

// ---------------- device globals ----------------
__device__ __nv_bfloat16 xh_b[T_SAMPLES];          // 16 MB
__device__ __nv_bfloat16 xl_b[T_SAMPLES];          // 16 MB
// B fragments: [chunk][k16(2)][bh(2)][nt(22)][lane(32)][reg(2) u32]
__device__ __align__(128) __nv_bfloat16 Bbig[CHUNKS * 2 * 2 * NTL * 32 * 4];
// split-K partials: [kq(4)][n(2048)][bin(96)] (wr, wi)
__device__ float2 Wpart[4 * FFTLEN * NBPAD];       // 6 MB

// ---------------- f32x2 helpers (prep) ----------------
__device__ __forceinline__ uint64_t pack2(float lo, float hi) {
    uint64_t r; asm("mov.b64 %0, {%1, %2};" : "=l"(r) : "f"(lo), "f"(hi)); return r;
}
__device__ __forceinline__ uint64_t dup2(float x) {
    uint64_t r; asm("mov.b64 %0, {%1, %1};" : "=l"(r) : "f"(x)); return r;
}
__device__ __forceinline__ void unpack2(uint64_t v, float& lo, float& hi) {
    asm("mov.b64 {%0, %1}, %2;" : "=f"(lo), "=f"(hi) : "l"(v));
}
__device__ __forceinline__ void ffma2(uint64_t& acc, uint64_t a, uint64_t b) {
    asm("fma.rn.f32x2 %0, %1, %2, %0;" : "+l"(acc) : "l"(a), "l"(b));
}

// =====================================================================
// storeB: write one (col, k) fused-W value into fragment order (verified)
// =====================================================================
__device__ __forceinline__ void storeB(int kg, int col,
                                       __nv_bfloat16 h, __nv_bfloat16 l) {
    int chunk = kg >> 5, k16 = (kg >> 4) & 1, kc = (kg & 15) >> 1;
    int reg = kc >> 2, byte = kg & 1;
    int lane = ((col & 7) << 2) | (kc & 3);
    int nt = col >> 3;
    int u32i = (((chunk * 2 + k16) * 2) * NTL + nt) * 64 + lane * 2 + reg;
    Bbig[u32i * 2 + byte] = h;
    Bbig[(u32i + NTL * 64) * 2 + byte] = l;
}

// =====================================================================
// Kernel 1: merged prep.
//  CTAs [0,512): fused-W build, split-K x4. cid = colblk(128) + 128*kq.
//  CTAs [512, 512+4096): x bf16 hi/lo split (hides under W build).
// =====================================================================
__global__ void __launch_bounds__(256) prep_all(
    const float* __restrict__ x,
    const float* __restrict__ kr, const float* __restrict__ ki,
    const float* __restrict__ wcos, const float* __restrict__ wsin)
{
    __shared__ float kct[32 * NBPAD * 2];
    __shared__ float wct[32 * 16 * 2];
    const int tid = threadIdx.x;

    if (blockIdx.x >= 512) {
        // ---------- x split ----------
        int i = ((blockIdx.x - 512) * 256 + tid) * 8;
        float4 a = *reinterpret_cast<const float4*>(x + i);
        float4 c = *reinterpret_cast<const float4*>(x + i + 4);
        float v[8] = {a.x, a.y, a.z, a.w, c.x, c.y, c.z, c.w};
#pragma unroll
        for (int j = 0; j < 4; j++) {
            __nv_bfloat16 h0 = __float2bfloat16(v[2 * j]);
            __nv_bfloat16 h1 = __float2bfloat16(v[2 * j + 1]);
            __nv_bfloat16 l0 = __float2bfloat16(v[2 * j]     - __bfloat162float(h0));
            __nv_bfloat16 l1 = __float2bfloat16(v[2 * j + 1] - __bfloat162float(h1));
            *reinterpret_cast<__nv_bfloat162*>(xh_b + i + 2 * j) = __nv_bfloat162(h0, h1);
            *reinterpret_cast<__nv_bfloat162*>(xl_b + i + 2 * j) = __nv_bfloat162(l0, l1);
        }
        return;
    }

    // ---------- fused-W build (split-K) ----------
    const int n_t    = tid & 15;
    const int bin_t  = tid >> 4;
    const int colblk = blockIdx.x & 127;
    const int kq     = blockIdx.x >> 7;          // 0..3
    const int n0     = colblk * 16;
    const int t0     = kq * 8;
    const int t1     = (kq == 3) ? 33 : (kq * 8 + 8);   // 33 tiles total

    uint64_t acc[6];
#pragma unroll
    for (int i = 0; i < 6; i++) acc[i] = 0ull;

    for (int kt = t0; kt < t1; kt++) {
        const int k0 = kt * 32;
        __syncthreads();
        for (int i = tid; i < NBPAD * 32; i += 256) {
            int b = i >> 5, kl = i & 31, kg = k0 + kl;
            float vr = 0.f, vi = 0.f;
            if (b < N_BINS && kg < FREQ_BINS) {
                vr = kr[b * FREQ_BINS + kg];
                vi = ki[b * FREQ_BINS + kg];
            }
            kct[kl * (NBPAD * 2) + b * 2]     = vr;
            kct[kl * (NBPAD * 2) + b * 2 + 1] = vi;
        }
        for (int i = tid; i < 32 * 16; i += 256) {
            int kl = i >> 4, nn = i & 15, kg = k0 + kl;
            float c = 0.f, s = 0.f;
            if (kg < FREQ_BINS) {
                c = wcos[kg * FFTLEN + n0 + nn];
                s = wsin[kg * FFTLEN + n0 + nn];
            }
            wct[kl * 32 + nn * 2]     = c;
            wct[kl * 32 + nn * 2 + 1] = s;
        }
        __syncthreads();
#pragma unroll 4
        for (int kl = 0; kl < 32; kl++) {
            float c = wct[kl * 32 + n_t * 2];
            float s = wct[kl * 32 + n_t * 2 + 1];
            uint64_t cs  = pack2(c, s);
            uint64_t mcs = pack2(-s, c);
            const float* kp = &kct[kl * (NBPAD * 2) + bin_t * 12];
#pragma unroll
            for (int i = 0; i < 6; i++) {
                float vkr = kp[i * 2], vki = kp[i * 2 + 1];
                ffma2(acc[i], dup2(vkr), cs);
                ffma2(acc[i], dup2(vki), mcs);
            }
        }
    }
    const int kg = n0 + n_t;
    float2* wp = Wpart + (size_t)(kq * FFTLEN + kg) * NBPAD;
#pragma unroll
    for (int i = 0; i < 6; i++) {
        int b = bin_t * 6 + i;
        float wr, wi; unpack2(acc[i], wr, wi);
        wp[b] = make_float2(wr, wi);
    }
}

// =====================================================================
// Kernel 2: combine split-K partials -> bf16 hi/lo -> Bbig fragments
// =====================================================================
__global__ void __launch_bounds__(256) combine_k(void) {
    int idx = blockIdx.x * 256 + threadIdx.x;     // over 2048*96
    int n = idx / NBPAD, b = idx % NBPAD;
    if (b >= N_BINS) return;
    float wr = 0.f, wi = 0.f;
#pragma unroll
    for (int q = 0; q < 4; q++) {
        float2 v = Wpart[(size_t)(q * FFTLEN + n) * NBPAD + b];
        wr += v.x; wi += v.y;
    }
    __nv_bfloat16 hr = __float2bfloat16(wr);
    __nv_bfloat16 lr = __float2bfloat16(wr - __bfloat162float(hr));
    __nv_bfloat16 hw = __float2bfloat16(wi);
    __nv_bfloat16 lw = __float2bfloat16(wi - __bfloat162float(hw));
    storeB(n, 2 * b,     hr, lr);
    storeB(n, 2 * b + 1, hw, lw);
}

// =====================================================================
// Main GEMM: CTA = 64 frames x 176 cols, 128 threads (4 warps = 2m x 2n).
// Warp tile 32 x 88: mt=2 mtiles, nt=11 ntiles, K split 3-product bf16.
// 3 CTAs/SM (60 KB x 3 = 180 KB smem).
// =====================================================================
#define A_ST   2048                 // u32 per A stage (8 KB)
#define B_ST   (2 * 2 * NTL * 64)   // 5632 u32 (22 KB)
#define STAGE  (A_ST + B_ST)        // 7680 u32 (30 KB)
#define MM_SMEM (2 * STAGE * 4)     // 61440 bytes

__device__ __forceinline__ void mma16816(float* d, const uint32_t* a,
                                         const uint32_t* b) {
    asm volatile(
        "mma.sync.aligned.m16n8k16.row.col.f32.bf16.bf16.f32 "
        "{%0,%1,%2,%3}, {%4,%5,%6,%7}, {%8,%9}, {%0,%1,%2,%3};"
        : "+f"(d[0]), "+f"(d[1]), "+f"(d[2]), "+f"(d[3])
        : "r"(a[0]), "r"(a[1]), "r"(a[2]), "r"(a[3]), "r"(b[0]), "r"(b[1]));
}

__device__ __forceinline__ void lda(int c, int f0, int tid, uint32_t* va) {
    const int row = tid & 63, half = tid >> 6;
    const __nv_bfloat16* src = half ? xl_b : xh_b;
    const int g = (f0 + row) * HOP + c * 32;
    const uint4* p = reinterpret_cast<const uint4*>(src + g);
#pragma unroll
    for (int i = 0; i < 4; i++) {
        uint4 t = make_uint4(0u, 0u, 0u, 0u);
        if (g + i * 8 + 7 < T_SAMPLES) t = p[i];
        va[i * 4 + 0] = t.x; va[i * 4 + 1] = t.y;
        va[i * 4 + 2] = t.z; va[i * 4 + 3] = t.w;
    }
}

__device__ __forceinline__ void sts_a(const uint32_t* va, uint32_t* bufA, int tid) {
    const int row = tid & 63, half = tid >> 6;
    const int mtile = row >> 4;
    const int rb = (row >> 3) & 1;
    const int rl = row & 7;
#pragma unroll
    for (int cp = 0; cp < 16; cp++) {
        int k16 = cp >> 3, kc = cp & 7;
        int ln  = (rl << 2) | (kc & 3);
        int reg = ((kc >> 2) << 1) | rb;
        int p   = (ln << 2) | reg;
        p ^= ((p >> 5) & 3) << 2;          // bank swizzle
        bufA[((k16 * 2 + half) * 4 + mtile) * 128 + p] = va[cp];
    }
}

__global__ void __launch_bounds__(128, 3) cqt_mma(float* __restrict__ out) {
    extern __shared__ uint32_t sm[];
    const int tid  = threadIdx.x;
    const int lane = tid & 31, wid = tid >> 5;
    const int wm   = wid & 1,  wn  = wid >> 1;
    const int f0   = blockIdx.x * 64;

    float acc[2][11][4];
#pragma unroll
    for (int a = 0; a < 2; a++)
#pragma unroll
        for (int b = 0; b < 11; b++)
#pragma unroll
            for (int d = 0; d < 4; d++) acc[a][b][d] = 0.f;

    uint32_t va[16];

    // prologue: A(0) -> stage0, B(0) in flight, A(1) in regs
    lda(0, f0, tid, va);
    sts_a(va, sm, tid);
    {
        const char* bs = reinterpret_cast<const char*>(Bbig);
        uint32_t bd;
        asm("{ .reg .u64 t; cvta.to.shared.u64 t, %1; cvt.u32.u64 %0, t; }"
            : "=r"(bd) : "l"((const void*)(sm + A_ST)));
#pragma unroll
        for (int i = 0; i < 11; i++) {
            int e = tid + i * 128;
            asm volatile("cp.async.ca.shared.global [%0], [%1], 16;"
                         :: "r"(bd + e * 16), "l"(bs + e * 16) : "memory");
        }
        asm volatile("cp.async.commit_group;" ::: "memory");
    }
    lda(1, f0, tid, va);

    for (int c = 0; c < CHUNKS; c++) {
        asm volatile("cp.async.wait_group 0;" ::: "memory");
        __syncthreads();   // A(c)+B(c) visible; compute(c-1) done by all

        if (c < CHUNKS - 1) {
            uint32_t* nbuf = sm + ((c + 1) & 1) * STAGE;
            sts_a(va, nbuf, tid);
            const char* bs = reinterpret_cast<const char*>(Bbig)
                             + (size_t)(c + 1) * (B_ST * 4);
            uint32_t bd;
            asm("{ .reg .u64 t; cvta.to.shared.u64 t, %1; cvt.u32.u64 %0, t; }"
                : "=r"(bd) : "l"((const void*)(nbuf + A_ST)));
#pragma unroll
            for (int i = 0; i < 11; i++) {
                int e = tid + i * 128;
                asm volatile("cp.async.ca.shared.global [%0], [%1], 16;"
                             :: "r"(bd + e * 16), "l"(bs + e * 16) : "memory");
            }
            asm volatile("cp.async.commit_group;" ::: "memory");
        }
        if (c < CHUNKS - 2) lda(c + 2, f0, tid, va);

        const uint32_t* A = sm + (c & 1) * STAGE;
        const uint32_t* B = A + A_ST;
#pragma unroll
        for (int k16 = 0; k16 < 2; k16++) {
            uint32_t ah[2][4], al[2][4];
            const int psw = (lane * 4) ^ ((((lane * 4) >> 5) & 3) << 2);
#pragma unroll
            for (int mt = 0; mt < 2; mt++) {
                uint4 qh = *reinterpret_cast<const uint4*>(
                    A + ((k16 * 2 + 0) * 4 + wm * 2 + mt) * 128 + psw);
                ah[mt][0] = qh.x; ah[mt][1] = qh.y; ah[mt][2] = qh.z; ah[mt][3] = qh.w;
                uint4 ql = *reinterpret_cast<const uint4*>(
                    A + ((k16 * 2 + 1) * 4 + wm * 2 + mt) * 128 + psw);
                al[mt][0] = ql.x; al[mt][1] = ql.y; al[mt][2] = ql.z; al[mt][3] = ql.w;
            }
#pragma unroll
            for (int nt = 0; nt < 11; nt++) {
                int bi = ((k16 * 2) * NTL + wn * 11 + nt) * 64 + lane * 2;
                uint2 qh = *reinterpret_cast<const uint2*>(B + bi);
                uint2 ql = *reinterpret_cast<const uint2*>(B + bi + NTL * 64);
                uint32_t bh[2] = {qh.x, qh.y};
                uint32_t bl[2] = {ql.x, ql.y};
                mma16816(acc[0][nt], ah[0], bh);
                mma16816(acc[1][nt], ah[1], bh);
                mma16816(acc[0][nt], al[0], bh);
                mma16816(acc[1][nt], al[1], bh);
                mma16816(acc[0][nt], ah[0], bl);
                mma16816(acc[1][nt], ah[1], bl);
            }
        }
    }

    // ---- epilogue: magnitude + store ----
#pragma unroll
    for (int mt = 0; mt < 2; mt++) {
        int fr = f0 + wm * 32 + mt * 16 + (lane >> 2);
#pragma unroll
        for (int nt = 0; nt < 11; nt++) {
            int bin = wn * 44 + nt * 4 + (lane & 3);
            if (bin < N_BINS) {
                float* d = acc[mt][nt];
                if (fr < N_FRAMES)
                    out[bin * N_FRAMES + fr] = sqrtf(d[0] * d[0] + d[1] * d[1]);
                if (fr + 8 < N_FRAMES)
                    out[bin * N_FRAMES + fr + 8] = sqrtf(d[2] * d[2] + d[3] * d[3]);
            }
        }
    }
}

// =====================================================================
extern "C" void kernel_launch(void* const* d_in, const int* in_sizes, int n_in,
                              void* d_out, int out_size)
{
    const float* x    = (const float*)d_in[0];
    const float* wcos = (const float*)d_in[1];
    const float* wsin = (const float*)d_in[2];
    const float* kr   = (const float*)d_in[3];
    const float* ki   = (const float*)d_in[4];
    float* out = (float*)d_out;

    prep_all<<<512 + T_SAMPLES / 2048, 256>>>(x, kr, ki, wcos, wsin);
    combine_k<<<(FFTLEN * NBPAD) / 256, 256>>>();

    cudaFuncSetAttribute(cqt_mma, cudaFuncAttributeMaxDynamicSharedMemorySize,
                         MM_SMEM);
    cqt_mma<<<16384 / 64, 128, MM_SMEM>>>(out);
}

// round 10
// speedup vs baseline: 2.9046x; 1.2770x over previous
#include <cuda_runtime.h>
#include <cuda_bf16.h>
#include <stdint.h>

// ---------------- problem constants ----------------
#define N_BINS    84
#define FFTLEN    2048
#define FREQ_BINS 1025
#define HOP       512
#define T_SAMPLES 8388608
#define N_FRAMES  16381
#define CHUNKS    64          // 64 chunks x 32 base-k = 2048
#define NTL       22          // ntiles: 176 cols = 88 re/im pairs >= 84 bins
#define NBPAD     96          // bins padded (16*6)
#define KQ        8           // split-K ways for W build

// ---------------- device globals ----------------
__device__ __nv_bfloat16 xh_b[T_SAMPLES];          // 16 MB
__device__ __nv_bfloat16 xl_b[T_SAMPLES];          // 16 MB
// B fragments: [chunk][k16(2)][bh(2)][nt(22)][lane(32)][reg(2) u32]
__device__ __align__(128) __nv_bfloat16 Bbig[CHUNKS * 2 * 2 * NTL * 32 * 4];
// split-K partials: [kq(8)][n(2048)][bin(96)] (wr, wi)
__device__ float2 Wpart[KQ * FFTLEN * NBPAD];      // 12.6 MB

// ---------------- f32x2 helpers (prep) ----------------
__device__ __forceinline__ uint64_t pack2(float lo, float hi) {
    uint64_t r; asm("mov.b64 %0, {%1, %2};" : "=l"(r) : "f"(lo), "f"(hi)); return r;
}
__device__ __forceinline__ uint64_t dup2(float x) {
    uint64_t r; asm("mov.b64 %0, {%1, %1};" : "=l"(r) : "f"(x)); return r;
}
__device__ __forceinline__ void unpack2(uint64_t v, float& lo, float& hi) {
    asm("mov.b64 {%0, %1}, %2;" : "=f"(lo), "=f"(hi) : "l"(v));
}
__device__ __forceinline__ void ffma2(uint64_t& acc, uint64_t a, uint64_t b) {
    asm("fma.rn.f32x2 %0, %1, %2, %0;" : "+l"(acc) : "l"(a), "l"(b));
}

// =====================================================================
// storeB: write one (col, k) fused-W value into fragment order (verified)
// =====================================================================
__device__ __forceinline__ void storeB(int kg, int col,
                                       __nv_bfloat16 h, __nv_bfloat16 l) {
    int chunk = kg >> 5, k16 = (kg >> 4) & 1, kc = (kg & 15) >> 1;
    int reg = kc >> 2, byte = kg & 1;
    int lane = ((col & 7) << 2) | (kc & 3);
    int nt = col >> 3;
    int u32i = (((chunk * 2 + k16) * 2) * NTL + nt) * 64 + lane * 2 + reg;
    Bbig[u32i * 2 + byte] = h;
    Bbig[(u32i + NTL * 64) * 2 + byte] = l;
}

// =====================================================================
// Kernel 1: merged prep.
//  CTAs [0,256): fused-W build, register-blocked 4n x 6bins per thread,
//                split-K x8.  bid = colblk(32) + 32*kq.
//  CTAs [256, 256+4096): x bf16 hi/lo split (hides under W build).
// =====================================================================
__global__ void __launch_bounds__(256) prep_all(
    const float* __restrict__ x,
    const float* __restrict__ kr, const float* __restrict__ ki,
    const float* __restrict__ wcos, const float* __restrict__ wsin)
{
    __shared__ float kct[32 * NBPAD * 2];   // [kl][b][{kr,ki}] 24 KB
    __shared__ float wct[32 * 64 * 2];      // [kl][nn][{c,s}]  16 KB
    const int tid = threadIdx.x;

    if (blockIdx.x >= 256) {
        // ---------- x split ----------
        int i = ((blockIdx.x - 256) * 256 + tid) * 8;
        float4 a = *reinterpret_cast<const float4*>(x + i);
        float4 c = *reinterpret_cast<const float4*>(x + i + 4);
        float v[8] = {a.x, a.y, a.z, a.w, c.x, c.y, c.z, c.w};
#pragma unroll
        for (int j = 0; j < 4; j++) {
            __nv_bfloat16 h0 = __float2bfloat16(v[2 * j]);
            __nv_bfloat16 h1 = __float2bfloat16(v[2 * j + 1]);
            __nv_bfloat16 l0 = __float2bfloat16(v[2 * j]     - __bfloat162float(h0));
            __nv_bfloat16 l1 = __float2bfloat16(v[2 * j + 1] - __bfloat162float(h1));
            *reinterpret_cast<__nv_bfloat162*>(xh_b + i + 2 * j) = __nv_bfloat162(h0, h1);
            *reinterpret_cast<__nv_bfloat162*>(xl_b + i + 2 * j) = __nv_bfloat162(l0, l1);
        }
        return;
    }

    // ---------- fused-W build (split-K, 4n x 6b per thread) ----------
    const int n_t    = tid & 15;
    const int bin_g  = tid >> 4;                 // 0..15, 6 bins each
    const int colblk = blockIdx.x & 31;          // 32 blocks x 64 n
    const int kq     = blockIdx.x >> 5;          // 0..7
    const int n0     = colblk * 64;
    const int t0     = kq * 4;
    const int t1     = (kq == KQ - 1) ? 33 : (t0 + 4);

    uint64_t acc[4][6];
#pragma unroll
    for (int j = 0; j < 4; j++)
#pragma unroll
        for (int i = 0; i < 6; i++) acc[j][i] = 0ull;

    for (int kt = t0; kt < t1; kt++) {
        const int k0 = kt * 32;
        __syncthreads();
        // fill kct (coalesced along kl)
        for (int i = tid; i < NBPAD * 32; i += 256) {
            int b = i >> 5, kl = i & 31, kg = k0 + kl;
            float vr = 0.f, vi = 0.f;
            if (b < N_BINS && kg < FREQ_BINS) {
                vr = kr[b * FREQ_BINS + kg];
                vi = ki[b * FREQ_BINS + kg];
            }
            kct[kl * (NBPAD * 2) + b * 2]     = vr;
            kct[kl * (NBPAD * 2) + b * 2 + 1] = vi;
        }
        // fill wct: 32 kl x 64 n
        for (int i = tid; i < 32 * 64; i += 256) {
            int kl = i >> 6, nn = i & 63, kg = k0 + kl;
            float c = 0.f, s = 0.f;
            if (kg < FREQ_BINS) {
                c = wcos[kg * FFTLEN + n0 + nn];
                s = wsin[kg * FFTLEN + n0 + nn];
            }
            wct[kl * 128 + nn * 2]     = c;
            wct[kl * 128 + nn * 2 + 1] = s;
        }
        __syncthreads();
#pragma unroll 2
        for (int kl = 0; kl < 32; kl++) {
            const float* wp_ = &wct[kl * 128 + n_t * 2];
            uint64_t cs[4], mcs[4];
#pragma unroll
            for (int j = 0; j < 4; j++) {
                float c = wp_[j * 32], s = wp_[j * 32 + 1];
                cs[j]  = pack2(c, s);
                mcs[j] = pack2(-s, c);
            }
            const float* kp = &kct[kl * (NBPAD * 2) + bin_g * 12];
#pragma unroll
            for (int i = 0; i < 6; i++) {
                uint64_t ukr = dup2(kp[i * 2]);
                uint64_t uki = dup2(kp[i * 2 + 1]);
#pragma unroll
                for (int j = 0; j < 4; j++) {
                    ffma2(acc[j][i], ukr, cs[j]);
                    ffma2(acc[j][i], uki, mcs[j]);
                }
            }
        }
    }
    // write partials
#pragma unroll
    for (int j = 0; j < 4; j++) {
        const int n = n0 + n_t + j * 16;
        float2* wp = Wpart + (size_t)(kq * FFTLEN + n) * NBPAD;
#pragma unroll
        for (int i = 0; i < 6; i++) {
            int b = bin_g * 6 + i;
            float wr, wi; unpack2(acc[j][i], wr, wi);
            wp[b] = make_float2(wr, wi);
        }
    }
}

// =====================================================================
// Kernel 2: combine split-K partials -> bf16 hi/lo -> Bbig fragments
// =====================================================================
__global__ void __launch_bounds__(256) combine_k(void) {
    int idx = blockIdx.x * 256 + threadIdx.x;     // over 2048*96
    int n = idx / NBPAD, b = idx % NBPAD;
    if (b >= N_BINS) return;
    float wr = 0.f, wi = 0.f;
#pragma unroll
    for (int q = 0; q < KQ; q++) {
        float2 v = Wpart[(size_t)(q * FFTLEN + n) * NBPAD + b];
        wr += v.x; wi += v.y;
    }
    __nv_bfloat16 hr = __float2bfloat16(wr);
    __nv_bfloat16 lr = __float2bfloat16(wr - __bfloat162float(hr));
    __nv_bfloat16 hw = __float2bfloat16(wi);
    __nv_bfloat16 lw = __float2bfloat16(wi - __bfloat162float(hw));
    storeB(n, 2 * b,     hr, lr);
    storeB(n, 2 * b + 1, hw, lw);
}

// =====================================================================
// Main GEMM: CTA = 64 frames x 176 cols, 128 threads (4 warps = 2m x 2n).
// Warp tile 32 x 88: mt=2 mtiles, nt=11 ntiles, K split 3-product bf16.
// 3 CTAs/SM (60 KB x 3 = 180 KB smem).  (verified R9)
// =====================================================================
#define A_ST   2048                 // u32 per A stage (8 KB)
#define B_ST   (2 * 2 * NTL * 64)   // 5632 u32 (22 KB)
#define STAGE  (A_ST + B_ST)        // 7680 u32 (30 KB)
#define MM_SMEM (2 * STAGE * 4)     // 61440 bytes

__device__ __forceinline__ void mma16816(float* d, const uint32_t* a,
                                         const uint32_t* b) {
    asm volatile(
        "mma.sync.aligned.m16n8k16.row.col.f32.bf16.bf16.f32 "
        "{%0,%1,%2,%3}, {%4,%5,%6,%7}, {%8,%9}, {%0,%1,%2,%3};"
        : "+f"(d[0]), "+f"(d[1]), "+f"(d[2]), "+f"(d[3])
        : "r"(a[0]), "r"(a[1]), "r"(a[2]), "r"(a[3]), "r"(b[0]), "r"(b[1]));
}

__device__ __forceinline__ void lda(int c, int f0, int tid, uint32_t* va) {
    const int row = tid & 63, half = tid >> 6;
    const __nv_bfloat16* src = half ? xl_b : xh_b;
    const int g = (f0 + row) * HOP + c * 32;
    const uint4* p = reinterpret_cast<const uint4*>(src + g);
#pragma unroll
    for (int i = 0; i < 4; i++) {
        uint4 t = make_uint4(0u, 0u, 0u, 0u);
        if (g + i * 8 + 7 < T_SAMPLES) t = p[i];
        va[i * 4 + 0] = t.x; va[i * 4 + 1] = t.y;
        va[i * 4 + 2] = t.z; va[i * 4 + 3] = t.w;
    }
}

__device__ __forceinline__ void sts_a(const uint32_t* va, uint32_t* bufA, int tid) {
    const int row = tid & 63, half = tid >> 6;
    const int mtile = row >> 4;
    const int rb = (row >> 3) & 1;
    const int rl = row & 7;
#pragma unroll
    for (int cp = 0; cp < 16; cp++) {
        int k16 = cp >> 3, kc = cp & 7;
        int ln  = (rl << 2) | (kc & 3);
        int reg = ((kc >> 2) << 1) | rb;
        int p   = (ln << 2) | reg;
        p ^= ((p >> 5) & 3) << 2;          // bank swizzle
        bufA[((k16 * 2 + half) * 4 + mtile) * 128 + p] = va[cp];
    }
}

__global__ void __launch_bounds__(128, 3) cqt_mma(float* __restrict__ out) {
    extern __shared__ uint32_t sm[];
    const int tid  = threadIdx.x;
    const int lane = tid & 31, wid = tid >> 5;
    const int wm   = wid & 1,  wn  = wid >> 1;
    const int f0   = blockIdx.x * 64;

    float acc[2][11][4];
#pragma unroll
    for (int a = 0; a < 2; a++)
#pragma unroll
        for (int b = 0; b < 11; b++)
#pragma unroll
            for (int d = 0; d < 4; d++) acc[a][b][d] = 0.f;

    uint32_t va[16];

    lda(0, f0, tid, va);
    sts_a(va, sm, tid);
    {
        const char* bs = reinterpret_cast<const char*>(Bbig);
        uint32_t bd;
        asm("{ .reg .u64 t; cvta.to.shared.u64 t, %1; cvt.u32.u64 %0, t; }"
            : "=r"(bd) : "l"((const void*)(sm + A_ST)));
#pragma unroll
        for (int i = 0; i < 11; i++) {
            int e = tid + i * 128;
            asm volatile("cp.async.ca.shared.global [%0], [%1], 16;"
                         :: "r"(bd + e * 16), "l"(bs + e * 16) : "memory");
        }
        asm volatile("cp.async.commit_group;" ::: "memory");
    }
    lda(1, f0, tid, va);

    for (int c = 0; c < CHUNKS; c++) {
        asm volatile("cp.async.wait_group 0;" ::: "memory");
        __syncthreads();

        if (c < CHUNKS - 1) {
            uint32_t* nbuf = sm + ((c + 1) & 1) * STAGE;
            sts_a(va, nbuf, tid);
            const char* bs = reinterpret_cast<const char*>(Bbig)
                             + (size_t)(c + 1) * (B_ST * 4);
            uint32_t bd;
            asm("{ .reg .u64 t; cvta.to.shared.u64 t, %1; cvt.u32.u64 %0, t; }"
                : "=r"(bd) : "l"((const void*)(nbuf + A_ST)));
#pragma unroll
            for (int i = 0; i < 11; i++) {
                int e = tid + i * 128;
                asm volatile("cp.async.ca.shared.global [%0], [%1], 16;"
                             :: "r"(bd + e * 16), "l"(bs + e * 16) : "memory");
            }
            asm volatile("cp.async.commit_group;" ::: "memory");
        }
        if (c < CHUNKS - 2) lda(c + 2, f0, tid, va);

        const uint32_t* A = sm + (c & 1) * STAGE;
        const uint32_t* B = A + A_ST;
#pragma unroll
        for (int k16 = 0; k16 < 2; k16++) {
            uint32_t ah[2][4], al[2][4];
            const int psw = (lane * 4) ^ ((((lane * 4) >> 5) & 3) << 2);
#pragma unroll
            for (int mt = 0; mt < 2; mt++) {
                uint4 qh = *reinterpret_cast<const uint4*>(
                    A + ((k16 * 2 + 0) * 4 + wm * 2 + mt) * 128 + psw);
                ah[mt][0] = qh.x; ah[mt][1] = qh.y; ah[mt][2] = qh.z; ah[mt][3] = qh.w;
                uint4 ql = *reinterpret_cast<const uint4*>(
                    A + ((k16 * 2 + 1) * 4 + wm * 2 + mt) * 128 + psw);
                al[mt][0] = ql.x; al[mt][1] = ql.y; al[mt][2] = ql.z; al[mt][3] = ql.w;
            }
#pragma unroll
            for (int nt = 0; nt < 11; nt++) {
                int bi = ((k16 * 2) * NTL + wn * 11 + nt) * 64 + lane * 2;
                uint2 qh = *reinterpret_cast<const uint2*>(B + bi);
                uint2 ql = *reinterpret_cast<const uint2*>(B + bi + NTL * 64);
                uint32_t bh[2] = {qh.x, qh.y};
                uint32_t bl[2] = {ql.x, ql.y};
                mma16816(acc[0][nt], ah[0], bh);
                mma16816(acc[1][nt], ah[1], bh);
                mma16816(acc[0][nt], al[0], bh);
                mma16816(acc[1][nt], al[1], bh);
                mma16816(acc[0][nt], ah[0], bl);
                mma16816(acc[1][nt], ah[1], bl);
            }
        }
    }

    // ---- epilogue: magnitude + store ----
#pragma unroll
    for (int mt = 0; mt < 2; mt++) {
        int fr = f0 + wm * 32 + mt * 16 + (lane >> 2);
#pragma unroll
        for (int nt = 0; nt < 11; nt++) {
            int bin = wn * 44 + nt * 4 + (lane & 3);
            if (bin < N_BINS) {
                float* d = acc[mt][nt];
                if (fr < N_FRAMES)
                    out[bin * N_FRAMES + fr] = sqrtf(d[0] * d[0] + d[1] * d[1]);
                if (fr + 8 < N_FRAMES)
                    out[bin * N_FRAMES + fr + 8] = sqrtf(d[2] * d[2] + d[3] * d[3]);
            }
        }
    }
}

// =====================================================================
extern "C" void kernel_launch(void* const* d_in, const int* in_sizes, int n_in,
                              void* d_out, int out_size)
{
    const float* x    = (const float*)d_in[0];
    const float* wcos = (const float*)d_in[1];
    const float* wsin = (const float*)d_in[2];
    const float* kr   = (const float*)d_in[3];
    const float* ki   = (const float*)d_in[4];
    float* out = (float*)d_out;

    prep_all<<<256 + T_SAMPLES / 2048, 256>>>(x, kr, ki, wcos, wsin);
    combine_k<<<(FFTLEN * NBPAD) / 256, 256>>>();

    cudaFuncSetAttribute(cqt_mma, cudaFuncAttributeMaxDynamicSharedMemorySize,
                         MM_SMEM);
    cqt_mma<<<16384 / 64, 128, MM_SMEM>>>(out);
}